// round 1
// baseline (speedup 1.0000x reference)
#include <cuda_runtime.h>
#include <stdint.h>

// WinnerTakeAll: per-row top-k (k=1000) keep-in-place, rows of 20000 fp32.
// One CTA per row. Row cached in SMEM as order-preserving uint32 keys,
// exact k-th value found via 3-pass radix select (11/11/10 bits),
// output written straight from SMEM (input read exactly once from DRAM).

#define DCOLS   20000
#define KKEEP   1000u
#define NT      512
#define NBINS   2048        // bins for pass A and B (11 bits)
#define CAND_MAX 4096

struct Smem {
    uint32_t keys[DCOLS];        // 80000 B
    uint32_t cand[CAND_MAX];     // 16384 B
    uint32_t hist[NBINS];        // 8192 B
    uint32_t cand_count;
    uint32_t bA, kkA;            // pass A result
    uint32_t bB, kkB;            // pass B result
    uint32_t bC, kkC, cntC;      // pass C result (exact value low bits, ties-to-keep, tie-total)
};

__device__ __forceinline__ uint32_t f2u(float f) {
    uint32_t b = __float_as_uint(f);
    return b ^ ((b & 0x80000000u) ? 0xFFFFFFFFu : 0x80000000u);
}
__device__ __forceinline__ float u2f(uint32_t u) {
    uint32_t b = (u & 0x80000000u) ? (u ^ 0x80000000u) : (u ^ 0xFFFFFFFFu);
    return __uint_as_float(b);
}

// Warp-aggregated histogram add (call with ALL 32 lanes of the warp active).
__device__ __forceinline__ void hist_add(uint32_t* hist, uint32_t bin, bool valid) {
    uint32_t key = valid ? bin : 0xFFFFFFFFu;
    unsigned m = __match_any_sync(0xFFFFFFFFu, key);
    int leader = __ffs(m) - 1;
    if (valid && (int)(threadIdx.x & 31) == leader)
        atomicAdd(&hist[bin], (uint32_t)__popc(m));
}

// Scan histogram from the TOP bin down; find bin containing the kk-th largest.
// Executed by warp 0 only. Writes: bin, remaining-within-bin, bin count.
__device__ __forceinline__ void select_from_top(const uint32_t* hist, int nbins, uint32_t kk,
                                                uint32_t* out_bin, uint32_t* out_kk, uint32_t* out_cnt) {
    int lane = threadIdx.x;  // 0..31 (only warp 0 calls)
    uint32_t cum = 0;
    for (int base = nbins - 32; base >= 0; base -= 32) {
        uint32_t v = hist[base + 31 - lane];   // lane 0 = highest bin in chunk
        uint32_t incl = v;
        #pragma unroll
        for (int off = 1; off < 32; off <<= 1) {
            uint32_t t = __shfl_up_sync(0xFFFFFFFFu, incl, off);
            if (lane >= off) incl += t;
        }
        uint32_t total = __shfl_sync(0xFFFFFFFFu, incl, 31);
        unsigned hm = __ballot_sync(0xFFFFFFFFu, cum + incl >= kk);
        if (hm) {
            int l = __ffs(hm) - 1;
            if (lane == l) {
                *out_bin = (uint32_t)(base + 31 - l);
                *out_kk  = kk - cum - (incl - v);   // elements still needed inside this bin
                *out_cnt = v;
            }
            return;
        }
        cum += total;
    }
    if (lane == 0) { *out_bin = 0; *out_kk = 1; *out_cnt = 1; }  // unreachable safety
}

extern "C" __global__ void __launch_bounds__(NT)
wta_kernel(const float* __restrict__ in, float* __restrict__ out, int rows) {
    extern __shared__ uint8_t smem_raw[];
    Smem* s = reinterpret_cast<Smem*>(smem_raw);

    const int row = blockIdx.x;
    if (row >= rows) return;
    const int tid = threadIdx.x;

    // ---- init ----
    for (int i = tid; i < NBINS; i += NT) s->hist[i] = 0;
    if (tid == 0) s->cand_count = 0;
    __syncthreads();

    // ---- load row (float4, coalesced) + pass-A histogram on top 11 bits ----
    const float4* rowp = reinterpret_cast<const float4*>(in + (size_t)row * DCOLS);
    uint4* keys4 = reinterpret_cast<uint4*>(s->keys);
    const int nvec = DCOLS / 4;                       // 5000
    const int niterA = (nvec + NT - 1) / NT;          // 10 (padded: all lanes loop)
    #pragma unroll 1
    for (int it = 0; it < niterA; it++) {
        int i = tid + it * NT;
        bool valid = i < nvec;
        uint32_t u0 = 0, u1 = 0, u2 = 0, u3 = 0;
        if (valid) {
            float4 v = rowp[i];
            u0 = f2u(v.x); u1 = f2u(v.y); u2 = f2u(v.z); u3 = f2u(v.w);
            keys4[i] = make_uint4(u0, u1, u2, u3);
        }
        hist_add(s->hist, u0 >> 21, valid);
        hist_add(s->hist, u1 >> 21, valid);
        hist_add(s->hist, u2 >> 21, valid);
        hist_add(s->hist, u3 >> 21, valid);
    }
    __syncthreads();

    if (tid < 32) select_from_top(s->hist, NBINS, KKEEP, &s->bA, &s->kkA, &s->cntC /*scratch*/);
    __syncthreads();

    const uint32_t b1 = s->bA;
    const uint32_t kk1 = s->kkA;

    // ---- compact candidates (elements whose top-11 bits == b1) ----
    for (int i = tid; i < DCOLS; i += NT) {
        uint32_t u = s->keys[i];
        if ((u >> 21) == b1) {
            uint32_t pos = atomicAdd(&s->cand_count, 1u);
            if (pos < CAND_MAX) s->cand[pos] = u;
        }
    }
    __syncthreads();

    const uint32_t ccount = s->cand_count;
    const bool use_cand = (ccount <= CAND_MAX);
    const int nitems = use_cand ? (int)ccount : DCOLS;

    // ---- pass B: bits [10,21) ----
    for (int i = tid; i < NBINS; i += NT) s->hist[i] = 0;
    __syncthreads();

    const int niterB = (nitems + NT - 1) / NT;
    #pragma unroll 1
    for (int it = 0; it < niterB; it++) {
        int i = tid + it * NT;
        bool valid = i < nitems;
        uint32_t u = 0;
        if (valid) u = use_cand ? s->cand[i] : s->keys[i];
        valid = valid && (use_cand || ((u >> 21) == b1));
        hist_add(s->hist, (u >> 10) & 0x7FFu, valid);
    }
    __syncthreads();

    if (tid < 32) select_from_top(s->hist, NBINS, kk1, &s->bB, &s->kkB, &s->cntC /*scratch*/);
    __syncthreads();

    const uint32_t b2 = s->bB;
    const uint32_t kk2 = s->kkB;
    const uint32_t pref22 = (b1 << 11) | b2;   // known top 22 bits (as value of u>>10)

    // ---- pass C: bits [0,10) -> exact threshold ----
    for (int i = tid; i < 1024; i += NT) s->hist[i] = 0;
    __syncthreads();

    #pragma unroll 1
    for (int it = 0; it < niterB; it++) {
        int i = tid + it * NT;
        bool valid = i < nitems;
        uint32_t u = 0;
        if (valid) u = use_cand ? s->cand[i] : s->keys[i];
        valid = valid && ((u >> 10) == pref22);
        hist_add(s->hist, u & 0x3FFu, valid);
    }
    __syncthreads();

    if (tid < 32) select_from_top(s->hist, 1024, kk2, &s->bC, &s->kkC, &s->cntC);
    __syncthreads();

    const uint32_t u_t = (b1 << 21) | (b2 << 10) | s->bC;  // exact k-th largest key
    const uint32_t A = s->kkC;        // how many ties (== u_t) to keep
    const uint32_t T = s->cntC;       // total ties
    const bool keep_all_ties = (A == T);   // overwhelmingly common path

    // ---- output pass: write from SMEM, zero the rest ----
    float4* outp = reinterpret_cast<float4*>(out + (size_t)row * DCOLS);
    #pragma unroll 1
    for (int i = tid; i < nvec; i += NT) {
        uint4 uu = keys4[i];
        float4 o;
        uint32_t uv[4] = {uu.x, uu.y, uu.z, uu.w};
        float ov[4];
        #pragma unroll
        for (int j = 0; j < 4; j++) {
            uint32_t u = uv[j];
            float r = 0.0f;
            if (u > u_t) {
                r = u2f(u);
            } else if (u == u_t) {
                if (keep_all_ties) {
                    r = u2f(u);
                } else {
                    // rare path: keep only the first A ties by index
                    int idx = i * 4 + j;
                    uint32_t rank = 0;
                    for (int q = 0; q < idx; q++) rank += (s->keys[q] == u_t);
                    if (rank < A) r = u2f(u);
                }
            }
            ov[j] = r;
        }
        o.x = ov[0]; o.y = ov[1]; o.z = ov[2]; o.w = ov[3];
        outp[i] = o;
    }
}

extern "C" void kernel_launch(void* const* d_in, const int* in_sizes, int n_in,
                              void* d_out, int out_size) {
    const float* in = (const float*)d_in[0];
    float* out = (float*)d_out;
    int rows = in_sizes[0] / DCOLS;   // 4096

    size_t smem_bytes = sizeof(Smem);
    cudaFuncSetAttribute(wta_kernel, cudaFuncAttributeMaxDynamicSharedMemorySize, (int)smem_bytes);
    wta_kernel<<<rows, NT, smem_bytes>>>(in, out, rows);
}

// round 2
// speedup vs baseline: 1.2721x; 1.2721x over previous
#include <cuda_runtime.h>
#include <stdint.h>

// WinnerTakeAll: per-row top-k (k=1000), rows of 20000 fp32, 4096 rows.
// One CTA per row, NO row cache in SMEM (row re-reads hit L2).
// Exact k-th largest found via radix select: 11-bit histogram over full row,
// then compact candidates (~hundreds) to SMEM, refine 11+10 bits on candidates.
// SMEM ~33KB -> 4 CTAs/SM -> 100% occupancy (latency-bound fix vs R1).

#define DCOLS    20000
#define KKEEP    1000u
#define NT       512
#define NBINS    2048
#define CAND_MAX 4096

struct Smem {
    uint32_t hist[NBINS];        // 8 KB
    uint32_t cand[CAND_MAX];     // 16 KB
    uint16_t cidx[CAND_MAX];     // 8 KB
    uint32_t cand_count;
    uint32_t bA, kkA;
    uint32_t bB, kkB;
    uint32_t bC, kkC, cntC;
};

__device__ __forceinline__ uint32_t f2u(float f) {
    uint32_t b = __float_as_uint(f);
    return b ^ ((b & 0x80000000u) ? 0xFFFFFFFFu : 0x80000000u);
}

// Warp-aggregated histogram add (ALL 32 lanes must participate).
__device__ __forceinline__ void hist_add(uint32_t* hist, uint32_t bin, bool valid) {
    uint32_t key = valid ? bin : 0xFFFFFFFFu;
    unsigned m = __match_any_sync(0xFFFFFFFFu, key);
    int leader = __ffs(m) - 1;
    if (valid && (int)(threadIdx.x & 31) == leader)
        atomicAdd(&hist[bin], (uint32_t)__popc(m));
}

// Scan histogram from TOP bin down for the kk-th largest. Warp 0 only.
__device__ __forceinline__ void select_from_top(const uint32_t* hist, int nbins, uint32_t kk,
                                                uint32_t* out_bin, uint32_t* out_kk, uint32_t* out_cnt) {
    int lane = threadIdx.x;
    uint32_t cum = 0;
    for (int base = nbins - 32; base >= 0; base -= 32) {
        uint32_t v = hist[base + 31 - lane];
        uint32_t incl = v;
        #pragma unroll
        for (int off = 1; off < 32; off <<= 1) {
            uint32_t t = __shfl_up_sync(0xFFFFFFFFu, incl, off);
            if (lane >= off) incl += t;
        }
        uint32_t total = __shfl_sync(0xFFFFFFFFu, incl, 31);
        unsigned hm = __ballot_sync(0xFFFFFFFFu, cum + incl >= kk);
        if (hm) {
            int l = __ffs(hm) - 1;
            if (lane == l) {
                *out_bin = (uint32_t)(base + 31 - l);
                *out_kk  = kk - cum - (incl - v);
                *out_cnt = v;
            }
            return;
        }
        cum += total;
    }
    if (lane == 0) { *out_bin = 0; *out_kk = 1; *out_cnt = 1; }
}

extern "C" __global__ void __launch_bounds__(NT, 4)
wta_kernel(const float* __restrict__ in, float* __restrict__ out, int rows) {
    __shared__ Smem s;

    const int row = blockIdx.x;
    if (row >= rows) return;
    const int tid = threadIdx.x;

    const float4* rowp = reinterpret_cast<const float4*>(in + (size_t)row * DCOLS);
    const int nvec = DCOLS / 4;                 // 5000
    const int niterA = (nvec + NT - 1) / NT;    // 10

    // ---- init ----
    for (int i = tid; i < NBINS; i += NT) s.hist[i] = 0;
    if (tid == 0) s.cand_count = 0;
    __syncthreads();

    // ---- pass A: histogram on top 11 bits (DRAM read, the only cold read) ----
    #pragma unroll 1
    for (int it = 0; it < niterA; it++) {
        int i = tid + it * NT;
        bool valid = i < nvec;
        uint32_t u0 = 0, u1 = 0, u2 = 0, u3 = 0;
        if (valid) {
            float4 v = rowp[i];
            u0 = f2u(v.x); u1 = f2u(v.y); u2 = f2u(v.z); u3 = f2u(v.w);
        }
        hist_add(s.hist, u0 >> 21, valid);
        hist_add(s.hist, u1 >> 21, valid);
        hist_add(s.hist, u2 >> 21, valid);
        hist_add(s.hist, u3 >> 21, valid);
    }
    __syncthreads();

    if (tid < 32) select_from_top(s.hist, NBINS, KKEEP, &s.bA, &s.kkA, &s.cntC);
    __syncthreads();

    const uint32_t b1 = s.bA;
    const uint32_t kk1 = s.kkA;

    // ---- compact candidates (top-11 bits == b1); row re-read hits L2 ----
    #pragma unroll 1
    for (int it = 0; it < niterA; it++) {
        int i = tid + it * NT;
        if (i < nvec) {
            float4 v = rowp[i];
            uint32_t uu[4] = { f2u(v.x), f2u(v.y), f2u(v.z), f2u(v.w) };
            #pragma unroll
            for (int j = 0; j < 4; j++) {
                if ((uu[j] >> 21) == b1) {
                    uint32_t pos = atomicAdd(&s.cand_count, 1u);
                    if (pos < CAND_MAX) { s.cand[pos] = uu[j]; s.cidx[pos] = (uint16_t)(i * 4 + j); }
                }
            }
        }
    }
    __syncthreads();

    const uint32_t ccount = s.cand_count;
    const bool use_cand = (ccount <= CAND_MAX);
    const int nitems = use_cand ? (int)ccount : DCOLS;
    const int niterB = (nitems + NT - 1) / NT;

    // ---- pass B: bits [10,21) ----
    for (int i = tid; i < NBINS; i += NT) s.hist[i] = 0;
    __syncthreads();

    const float* rowf = in + (size_t)row * DCOLS;
    #pragma unroll 1
    for (int it = 0; it < niterB; it++) {
        int i = tid + it * NT;
        bool valid = i < nitems;
        uint32_t u = 0;
        if (valid) u = use_cand ? s.cand[i] : f2u(rowf[i]);
        valid = valid && (use_cand || ((u >> 21) == b1));
        hist_add(s.hist, (u >> 10) & 0x7FFu, valid);
    }
    __syncthreads();

    if (tid < 32) select_from_top(s.hist, NBINS, kk1, &s.bB, &s.kkB, &s.cntC);
    __syncthreads();

    const uint32_t b2 = s.bB;
    const uint32_t kk2 = s.kkB;
    const uint32_t pref22 = (b1 << 11) | b2;

    // ---- pass C: bits [0,10) ----
    for (int i = tid; i < 1024; i += NT) s.hist[i] = 0;
    __syncthreads();

    #pragma unroll 1
    for (int it = 0; it < niterB; it++) {
        int i = tid + it * NT;
        bool valid = i < nitems;
        uint32_t u = 0;
        if (valid) u = use_cand ? s.cand[i] : f2u(rowf[i]);
        valid = valid && ((u >> 10) == pref22);
        hist_add(s.hist, u & 0x3FFu, valid);
    }
    __syncthreads();

    if (tid < 32) select_from_top(s.hist, 1024, kk2, &s.bC, &s.kkC, &s.cntC);
    __syncthreads();

    const uint32_t u_t = (b1 << 21) | (b2 << 10) | s.bC;  // exact k-th largest key
    const uint32_t A = s.kkC;           // ties to keep
    const uint32_t T = s.cntC;          // total ties
    const bool keep_all_ties = (A == T);

    // ---- output pass: re-read row (L2 hit), write result ----
    float4* outp = reinterpret_cast<float4*>(out + (size_t)row * DCOLS);
    #pragma unroll 1
    for (int it = 0; it < niterA; it++) {
        int i = tid + it * NT;
        if (i >= nvec) break;
        float4 v = rowp[i];
        float vv[4] = { v.x, v.y, v.z, v.w };
        uint32_t uu[4] = { f2u(v.x), f2u(v.y), f2u(v.z), f2u(v.w) };
        float ov[4];
        #pragma unroll
        for (int j = 0; j < 4; j++) {
            uint32_t u = uu[j];
            float r = 0.0f;
            if (u > u_t) {
                r = vv[j];
            } else if (u == u_t) {
                if (keep_all_ties) {
                    r = vv[j];
                } else {
                    // rare path: keep only the first A ties by original index
                    int idx = i * 4 + j;
                    uint32_t rank = 0;
                    if (use_cand) {
                        for (uint32_t q = 0; q < ccount; q++)
                            rank += (s.cand[q] == u_t && (int)s.cidx[q] < idx);
                    } else {
                        for (int q = 0; q < idx; q++)
                            rank += (f2u(rowf[q]) == u_t);
                    }
                    if (rank < A) r = vv[j];
                }
            }
            ov[j] = r;
        }
        float4 o; o.x = ov[0]; o.y = ov[1]; o.z = ov[2]; o.w = ov[3];
        outp[it * NT + tid] = o;
    }
}

extern "C" void kernel_launch(void* const* d_in, const int* in_sizes, int n_in,
                              void* d_out, int out_size) {
    const float* in = (const float*)d_in[0];
    float* out = (float*)d_out;
    int rows = in_sizes[0] / DCOLS;   // 4096
    wta_kernel<<<rows, NT>>>(in, out, rows);
}

// round 3
// speedup vs baseline: 1.9395x; 1.5247x over previous
#include <cuda_runtime.h>
#include <stdint.h>

// WinnerTakeAll: per-row top-k (k=1000), rows of 20000 fp32, 4096 rows.
// One CTA/row. Radix-select threshold:
//   Pass A: 11-bit histogram over POSITIVE elements only (threshold is positive
//           unless <k positives exist -> rare fallback adds negatives).
//   Pass 2: merged output+compact: write val/0, defer bin==b1 elems to SMEM.
//   Passes B/C: refine threshold on ~500 SMEM candidates.
//   Fixup:  scatter-write the deferred winners.
// 2 full-row reads (1 DRAM + 1 L2) + 1 write. SMEM ~33KB -> 4 CTAs/SM.

#define DCOLS    20000
#define KKEEP    1000u
#define NT       512
#define NBINS    2048
#define CAND_MAX 4096

struct Smem {
    uint32_t hist[NBINS];        // 8 KB
    uint32_t cand[CAND_MAX];     // 16 KB
    uint16_t cidx[CAND_MAX];     // 8 KB
    uint32_t cand_count;
    uint32_t nneg;
    uint32_t bA, kkA;
    uint32_t bB, kkB;
    uint32_t bC, kkC, cntC;
};

__device__ __forceinline__ uint32_t f2u(float f) {
    uint32_t b = __float_as_uint(f);
    return b ^ ((b & 0x80000000u) ? 0xFFFFFFFFu : 0x80000000u);
}
__device__ __forceinline__ float u2f(uint32_t u) {
    uint32_t b = (u & 0x80000000u) ? (u ^ 0x80000000u) : (u ^ 0xFFFFFFFFu);
    return __uint_as_float(b);
}

// Warp-aggregated histogram add (ALL 32 lanes participate).
__device__ __forceinline__ void hist_add(uint32_t* hist, uint32_t bin, bool valid) {
    uint32_t key = valid ? bin : 0xFFFFFFFFu;
    unsigned m = __match_any_sync(0xFFFFFFFFu, key);
    int leader = __ffs(m) - 1;
    if (valid && (int)(threadIdx.x & 31) == leader)
        atomicAdd(&hist[bin], (uint32_t)__popc(m));
}

// Scan histogram from TOP bin down for the kk-th largest. Warp 0 only.
__device__ __forceinline__ void select_from_top(const uint32_t* hist, int nbins, uint32_t kk,
                                                uint32_t* out_bin, uint32_t* out_kk, uint32_t* out_cnt) {
    int lane = threadIdx.x;
    uint32_t cum = 0;
    for (int base = nbins - 32; base >= 0; base -= 32) {
        uint32_t v = hist[base + 31 - lane];
        uint32_t incl = v;
        #pragma unroll
        for (int off = 1; off < 32; off <<= 1) {
            uint32_t t = __shfl_up_sync(0xFFFFFFFFu, incl, off);
            if (lane >= off) incl += t;
        }
        uint32_t total = __shfl_sync(0xFFFFFFFFu, incl, 31);
        unsigned hm = __ballot_sync(0xFFFFFFFFu, cum + incl >= kk);
        if (hm) {
            int l = __ffs(hm) - 1;
            if (lane == l) {
                *out_bin = (uint32_t)(base + 31 - l);
                *out_kk  = kk - cum - (incl - v);
                *out_cnt = v;
            }
            return;
        }
        cum += total;
    }
    if (lane == 0) { *out_bin = 0; *out_kk = 1; *out_cnt = 1; }
}

extern "C" __global__ void __launch_bounds__(NT, 4)
wta_kernel(const float* __restrict__ in, float* __restrict__ out, int rows) {
    __shared__ Smem s;

    const int row = blockIdx.x;
    if (row >= rows) return;
    const int tid = threadIdx.x;

    const float4* rowp = reinterpret_cast<const float4*>(in + (size_t)row * DCOLS);
    const float*  rowf = in + (size_t)row * DCOLS;
    float4* outp = reinterpret_cast<float4*>(out + (size_t)row * DCOLS);
    const int nvec = DCOLS / 4;                 // 5000
    const int niter = (nvec + NT - 1) / NT;     // 10

    // ---- init ----
    {
        uint4* h4 = reinterpret_cast<uint4*>(s.hist);
        h4[tid] = make_uint4(0, 0, 0, 0);       // 512*16B = 8KB = whole hist
    }
    if (tid == 0) { s.cand_count = 0; s.nneg = 0; }
    __syncthreads();

    // ---- pass A: histogram POSITIVE elements only (DRAM read) ----
    uint32_t local_neg = 0;
    #pragma unroll 2
    for (int it = 0; it < niter; it++) {
        int i = tid + it * NT;
        bool valid = i < nvec;
        uint32_t b0 = 0x80000000u, b1r = 0x80000000u, b2r = 0x80000000u, b3r = 0x80000000u;
        if (valid) {
            float4 v = rowp[i];
            b0 = __float_as_uint(v.x); b1r = __float_as_uint(v.y);
            b2r = __float_as_uint(v.z); b3r = __float_as_uint(v.w);
        }
        bool p0 = (int)b0 >= 0, p1 = (int)b1r >= 0, p2 = (int)b2r >= 0, p3 = (int)b3r >= 0;
        if (valid) local_neg += (!p0) + (!p1) + (!p2) + (!p3);
        // positive f2u bin == (bits>>21) + 1024
        hist_add(s.hist, (b0  >> 21) + 1024u, valid && p0);
        hist_add(s.hist, (b1r >> 21) + 1024u, valid && p1);
        hist_add(s.hist, (b2r >> 21) + 1024u, valid && p2);
        hist_add(s.hist, (b3r >> 21) + 1024u, valid && p3);
    }
    // reduce negative count (registers -> 1 atomic per warp)
    #pragma unroll
    for (int off = 16; off > 0; off >>= 1)
        local_neg += __shfl_down_sync(0xFFFFFFFFu, local_neg, off);
    if ((tid & 31) == 0 && local_neg) atomicAdd(&s.nneg, local_neg);
    __syncthreads();

    // ---- rare fallback: fewer than k positives -> add negative bins ----
    if (DCOLS - s.nneg < KKEEP) {
        #pragma unroll 1
        for (int it = 0; it < niter; it++) {
            int i = tid + it * NT;
            bool valid = i < nvec;
            uint32_t u0 = 0, u1 = 0, u2 = 0, u3 = 0;
            bool n0 = false, n1 = false, n2 = false, n3 = false;
            if (valid) {
                float4 v = rowp[i];
                uint32_t b0 = __float_as_uint(v.x), b1r = __float_as_uint(v.y);
                uint32_t b2r = __float_as_uint(v.z), b3r = __float_as_uint(v.w);
                n0 = (int)b0 < 0; n1 = (int)b1r < 0; n2 = (int)b2r < 0; n3 = (int)b3r < 0;
                u0 = (~b0) >> 21; u1 = (~b1r) >> 21; u2 = (~b2r) >> 21; u3 = (~b3r) >> 21;
            }
            hist_add(s.hist, u0, valid && n0);
            hist_add(s.hist, u1, valid && n1);
            hist_add(s.hist, u2, valid && n2);
            hist_add(s.hist, u3, valid && n3);
        }
        __syncthreads();
    }

    if (tid < 32) select_from_top(s.hist, NBINS, KKEEP, &s.bA, &s.kkA, &s.cntC);
    __syncthreads();

    const uint32_t b1 = s.bA;       // 11-bit bin (f2u key space) containing k-th largest
    const uint32_t kk1 = s.kkA;     // rank needed within bin b1

    // ---- merged pass 2: write output (defer bin==b1), compact candidates (L2 read) ----
    #pragma unroll 2
    for (int it = 0; it < niter; it++) {
        int i = tid + it * NT;
        if (i >= nvec) break;
        float4 v = rowp[i];
        float vv[4] = { v.x, v.y, v.z, v.w };
        uint32_t uu[4] = { f2u(v.x), f2u(v.y), f2u(v.z), f2u(v.w) };
        float ov[4];
        #pragma unroll
        for (int j = 0; j < 4; j++) {
            uint32_t bin = uu[j] >> 21;
            ov[j] = (bin > b1) ? vv[j] : 0.0f;
            if (bin == b1) {
                uint32_t pos = atomicAdd(&s.cand_count, 1u);
                if (pos < CAND_MAX) { s.cand[pos] = uu[j]; s.cidx[pos] = (uint16_t)(i * 4 + j); }
            }
        }
        float4 o; o.x = ov[0]; o.y = ov[1]; o.z = ov[2]; o.w = ov[3];
        outp[i] = o;
    }
    __syncthreads();

    const uint32_t ccount = s.cand_count;
    const bool use_cand = (ccount <= CAND_MAX);
    const int nitems = use_cand ? (int)ccount : DCOLS;
    const int niterB = (nitems + NT - 1) / NT;

    // ---- pass B: bits [10,21) on candidates ----
    {
        uint4* h4 = reinterpret_cast<uint4*>(s.hist);
        h4[tid] = make_uint4(0, 0, 0, 0);
    }
    __syncthreads();

    #pragma unroll 1
    for (int it = 0; it < niterB; it++) {
        int i = tid + it * NT;
        bool valid = i < nitems;
        uint32_t u = 0;
        if (valid) u = use_cand ? s.cand[i] : f2u(rowf[i]);
        valid = valid && (use_cand || ((u >> 21) == b1));
        hist_add(s.hist, (u >> 10) & 0x7FFu, valid);
    }
    __syncthreads();

    if (tid < 32) select_from_top(s.hist, NBINS, kk1, &s.bB, &s.kkB, &s.cntC);
    __syncthreads();

    const uint32_t b2 = s.bB;
    const uint32_t kk2 = s.kkB;
    const uint32_t pref22 = (b1 << 11) | b2;

    // ---- pass C: bits [0,10) ----
    for (int i = tid; i < 1024; i += NT) s.hist[i] = 0;
    __syncthreads();

    #pragma unroll 1
    for (int it = 0; it < niterB; it++) {
        int i = tid + it * NT;
        bool valid = i < nitems;
        uint32_t u = 0;
        if (valid) u = use_cand ? s.cand[i] : f2u(rowf[i]);
        valid = valid && ((u >> 10) == pref22);
        hist_add(s.hist, u & 0x3FFu, valid);
    }
    __syncthreads();

    if (tid < 32) select_from_top(s.hist, 1024, kk2, &s.bC, &s.kkC, &s.cntC);
    __syncthreads();

    const uint32_t u_t = (b1 << 21) | (b2 << 10) | s.bC;  // exact k-th largest key
    const uint32_t A = s.kkC;          // ties to keep
    const uint32_t T = s.cntC;         // total ties
    const bool keep_all_ties = (A == T);

    float* outf = out + (size_t)row * DCOLS;

    // ---- fixup: scatter-write deferred winners ----
    if (use_cand) {
        for (uint32_t q = tid; q < ccount; q += NT) {
            uint32_t u = s.cand[q];
            bool keep = (u > u_t);
            if (!keep && u == u_t) {
                if (keep_all_ties) keep = true;
                else {
                    uint32_t rank = 0;
                    for (uint32_t p = 0; p < ccount; p++)
                        rank += (s.cand[p] == u_t && s.cidx[p] < s.cidx[q]);
                    keep = (rank < A);
                }
            }
            if (keep) outf[s.cidx[q]] = u2f(u);
        }
    } else {
        // overflow fallback: scan whole row for bin==b1 winners
        for (int i = tid; i < DCOLS; i += NT) {
            uint32_t u = f2u(rowf[i]);
            if ((u >> 21) != b1) continue;
            bool keep = (u > u_t);
            if (!keep && u == u_t) {
                if (keep_all_ties) keep = true;
                else {
                    uint32_t rank = 0;
                    for (int q = 0; q < i; q++) rank += (f2u(rowf[q]) == u_t);
                    keep = (rank < A);
                }
            }
            if (keep) outf[i] = u2f(u);
        }
    }
}

extern "C" void kernel_launch(void* const* d_in, const int* in_sizes, int n_in,
                              void* d_out, int out_size) {
    const float* in = (const float*)d_in[0];
    float* out = (float*)d_out;
    int rows = in_sizes[0] / DCOLS;   // 4096
    wta_kernel<<<rows, NT>>>(in, out, rows);
}

// round 4
// speedup vs baseline: 2.2651x; 1.1679x over previous
#include <cuda_runtime.h>
#include <stdint.h>

// WinnerTakeAll: per-row top-k (k=1000), rows of 20000 fp32, 4096 rows.
// One CTA/row. Sample-bracketed exact selection:
//  1. Sample 2048 elems (coalesced), histogram sample on 11-bit key bins,
//     pick bracket bins b_hi (rank 52) and b_lo (rank 180).
//  2. ONE full-row pass: write output speculatively (val if bin>b_hi else 0),
//     compact bin in [b_lo,b_hi] to SMEM (~1.5K), count c_above.
//  3. Verify c_above < k <= c_above+ccount and no overflow; else SLOW PATH
//     (full MATCH-histogram radix select, rewrites whole row) for correctness.
//  4. Exact k-th key via 11/11/10 radix over SMEM candidates; scatter fixup.
// 1 DRAM read + 1 write = bandwidth floor. SMEM ~33KB -> 4 CTAs/SM.

#define DCOLS    20000
#define KKEEP    1000u
#define NT       512
#define NBINS    2048
#define CAND_MAX 4096
#define R_HI     52u      // sample rank for upper bracket bin
#define R_LO     180u     // sample rank for lower bracket bin

struct Smem {
    uint32_t hist[NBINS];        // 8 KB
    uint32_t cand[CAND_MAX];     // 16 KB
    uint16_t cidx[CAND_MAX];     // 8 KB
    uint32_t cand_count;
    uint32_t c_above;
    uint32_t bHi, bLo, scr0, scr1;
    uint32_t bA, kkA;
    uint32_t bB, kkB;
    uint32_t bC, kkC, cntC;
};

__device__ __forceinline__ uint32_t f2u(float f) {
    uint32_t b = __float_as_uint(f);
    return b ^ ((b & 0x80000000u) ? 0xFFFFFFFFu : 0x80000000u);
}
__device__ __forceinline__ float u2f(uint32_t u) {
    uint32_t b = (u & 0x80000000u) ? (u ^ 0x80000000u) : (u ^ 0xFFFFFFFFu);
    return __uint_as_float(b);
}

// Warp-aggregated histogram add (ALL 32 lanes participate).
__device__ __forceinline__ void hist_add(uint32_t* hist, uint32_t bin, bool valid) {
    uint32_t key = valid ? bin : 0xFFFFFFFFu;
    unsigned m = __match_any_sync(0xFFFFFFFFu, key);
    int leader = __ffs(m) - 1;
    if (valid && (int)(threadIdx.x & 31) == leader)
        atomicAdd(&hist[bin], (uint32_t)__popc(m));
}

// Scan histogram from TOP bin down for the kk-th largest. Warp 0 only.
__device__ __forceinline__ void select_from_top(const uint32_t* hist, int nbins, uint32_t kk,
                                                uint32_t* out_bin, uint32_t* out_kk, uint32_t* out_cnt) {
    int lane = threadIdx.x & 31;
    uint32_t cum = 0;
    for (int base = nbins - 32; base >= 0; base -= 32) {
        uint32_t v = hist[base + 31 - lane];
        uint32_t incl = v;
        #pragma unroll
        for (int off = 1; off < 32; off <<= 1) {
            uint32_t t = __shfl_up_sync(0xFFFFFFFFu, incl, off);
            if (lane >= off) incl += t;
        }
        uint32_t total = __shfl_sync(0xFFFFFFFFu, incl, 31);
        unsigned hm = __ballot_sync(0xFFFFFFFFu, cum + incl >= kk);
        if (hm) {
            int l = __ffs(hm) - 1;
            if (lane == l) {
                *out_bin = (uint32_t)(base + 31 - l);
                *out_kk  = kk - cum - (incl - v);
                *out_cnt = v;
            }
            return;
        }
        cum += total;
    }
    if (lane == 0) { *out_bin = 0; *out_kk = 1; *out_cnt = 1; }
}

extern "C" __global__ void __launch_bounds__(NT, 4)
wta_kernel(const float* __restrict__ in, float* __restrict__ out, int rows) {
    __shared__ Smem s;

    const int row = blockIdx.x;
    if (row >= rows) return;
    const int tid = threadIdx.x;

    const float4* rowp = reinterpret_cast<const float4*>(in + (size_t)row * DCOLS);
    const float*  rowf = in + (size_t)row * DCOLS;
    float4* outp = reinterpret_cast<float4*>(out + (size_t)row * DCOLS);
    float*  outf = out + (size_t)row * DCOLS;
    const int nvec = DCOLS / 4;                 // 5000
    const int niter = (nvec + NT - 1) / NT;     // 10

    // ---- init ----
    {
        uint4* h4 = reinterpret_cast<uint4*>(s.hist);
        h4[tid] = make_uint4(0, 0, 0, 0);       // full 8KB hist
    }
    if (tid == 0) { s.cand_count = 0; s.c_above = 0; }
    __syncthreads();

    // ---- step 1: sample first 2048 elements (coalesced), histogram bins ----
    {
        float4 v = rowp[tid];                   // 512*4 = 2048 samples
        hist_add(s.hist, f2u(v.x) >> 21, true);
        hist_add(s.hist, f2u(v.y) >> 21, true);
        hist_add(s.hist, f2u(v.z) >> 21, true);
        hist_add(s.hist, f2u(v.w) >> 21, true);
    }
    __syncthreads();

    if (tid < 32) {
        select_from_top(s.hist, NBINS, R_HI, &s.bHi, &s.scr0, &s.scr1);
        __syncwarp();
        select_from_top(s.hist, NBINS, R_LO, &s.bLo, &s.scr0, &s.scr1);
    }
    __syncthreads();

    const uint32_t bHi = s.bHi;
    const uint32_t bLo = s.bLo;

    // clear hist for later candidate passes (hist unused until then)
    {
        uint4* h4 = reinterpret_cast<uint4*>(s.hist);
        h4[tid] = make_uint4(0, 0, 0, 0);
    }

    // ---- step 2: single full-row pass: speculative output + compact + count ----
    uint32_t my_above = 0;
    #pragma unroll 2
    for (int it = 0; it < niter; it++) {
        int i = tid + it * NT;
        if (i >= nvec) break;
        float4 v = rowp[i];
        float vv[4] = { v.x, v.y, v.z, v.w };
        uint32_t uu[4] = { f2u(v.x), f2u(v.y), f2u(v.z), f2u(v.w) };
        float ov[4];
        #pragma unroll
        for (int j = 0; j < 4; j++) {
            uint32_t bin = uu[j] >> 21;
            bool above = bin > bHi;
            ov[j] = above ? vv[j] : 0.0f;
            my_above += above;
            if (!above && bin >= bLo) {
                uint32_t pos = atomicAdd(&s.cand_count, 1u);
                if (pos < CAND_MAX) { s.cand[pos] = uu[j]; s.cidx[pos] = (uint16_t)(i * 4 + j); }
            }
        }
        float4 o; o.x = ov[0]; o.y = ov[1]; o.z = ov[2]; o.w = ov[3];
        outp[i] = o;
    }
    #pragma unroll
    for (int off = 16; off > 0; off >>= 1)
        my_above += __shfl_down_sync(0xFFFFFFFFu, my_above, off);
    if ((tid & 31) == 0 && my_above) atomicAdd(&s.c_above, my_above);
    __syncthreads();

    uint32_t c_above = s.c_above;
    uint32_t ccount  = s.cand_count;
    bool fast = (c_above < KKEEP) && (c_above + ccount >= KKEEP) && (ccount <= CAND_MAX);

    if (!fast) {
        // ================= SLOW PATH (rare; rewrites entire row) =================
        __syncthreads();
        {
            uint4* h4 = reinterpret_cast<uint4*>(s.hist);
            h4[tid] = make_uint4(0, 0, 0, 0);
        }
        if (tid == 0) s.cand_count = 0;
        __syncthreads();

        // full histogram on 11-bit key bins
        #pragma unroll 1
        for (int it = 0; it < niter; it++) {
            int i = tid + it * NT;
            bool valid = i < nvec;
            uint32_t u0 = 0, u1 = 0, u2 = 0, u3 = 0;
            if (valid) {
                float4 v = rowp[i];
                u0 = f2u(v.x); u1 = f2u(v.y); u2 = f2u(v.z); u3 = f2u(v.w);
            }
            hist_add(s.hist, u0 >> 21, valid);
            hist_add(s.hist, u1 >> 21, valid);
            hist_add(s.hist, u2 >> 21, valid);
            hist_add(s.hist, u3 >> 21, valid);
        }
        __syncthreads();
        if (tid < 32) select_from_top(s.hist, NBINS, KKEEP, &s.bA, &s.kkA, &s.cntC);
        __syncthreads();
        const uint32_t b1 = s.bA;
        const uint32_t kk1 = s.kkA;

        // merged output + compact
        #pragma unroll 1
        for (int it = 0; it < niter; it++) {
            int i = tid + it * NT;
            if (i >= nvec) break;
            float4 v = rowp[i];
            float vv[4] = { v.x, v.y, v.z, v.w };
            uint32_t uu[4] = { f2u(v.x), f2u(v.y), f2u(v.z), f2u(v.w) };
            float ov[4];
            #pragma unroll
            for (int j = 0; j < 4; j++) {
                uint32_t bin = uu[j] >> 21;
                ov[j] = (bin > b1) ? vv[j] : 0.0f;
                if (bin == b1) {
                    uint32_t pos = atomicAdd(&s.cand_count, 1u);
                    if (pos < CAND_MAX) { s.cand[pos] = uu[j]; s.cidx[pos] = (uint16_t)(i * 4 + j); }
                }
            }
            float4 o; o.x = ov[0]; o.y = ov[1]; o.z = ov[2]; o.w = ov[3];
            outp[i] = o;
        }
        __syncthreads();

        const uint32_t cc2 = s.cand_count;
        const bool use_cand = (cc2 <= CAND_MAX);
        const int nitems = use_cand ? (int)cc2 : DCOLS;
        const int niterB = (nitems + NT - 1) / NT;

        // refine bits [10,21)
        {
            uint4* h4 = reinterpret_cast<uint4*>(s.hist);
            h4[tid] = make_uint4(0, 0, 0, 0);
        }
        __syncthreads();
        #pragma unroll 1
        for (int it = 0; it < niterB; it++) {
            int i = tid + it * NT;
            bool valid = i < nitems;
            uint32_t u = 0;
            if (valid) u = use_cand ? s.cand[i] : f2u(rowf[i]);
            valid = valid && (use_cand || ((u >> 21) == b1));
            hist_add(s.hist, (u >> 10) & 0x7FFu, valid);
        }
        __syncthreads();
        if (tid < 32) select_from_top(s.hist, NBINS, kk1, &s.bB, &s.kkB, &s.cntC);
        __syncthreads();
        const uint32_t b2 = s.bB;
        const uint32_t kk2 = s.kkB;
        const uint32_t pref22 = (b1 << 11) | b2;

        // refine bits [0,10)
        for (int i = tid; i < 1024; i += NT) s.hist[i] = 0;
        __syncthreads();
        #pragma unroll 1
        for (int it = 0; it < niterB; it++) {
            int i = tid + it * NT;
            bool valid = i < nitems;
            uint32_t u = 0;
            if (valid) u = use_cand ? s.cand[i] : f2u(rowf[i]);
            valid = valid && ((u >> 10) == pref22);
            hist_add(s.hist, u & 0x3FFu, valid);
        }
        __syncthreads();
        if (tid < 32) select_from_top(s.hist, 1024, kk2, &s.bC, &s.kkC, &s.cntC);
        __syncthreads();

        const uint32_t u_t = (b1 << 21) | (b2 << 10) | s.bC;
        const uint32_t A = s.kkC;
        const uint32_t T = s.cntC;
        const bool keep_all_ties = (A == T);

        if (use_cand) {
            for (uint32_t q = tid; q < cc2; q += NT) {
                uint32_t u = s.cand[q];
                bool keep = (u > u_t);
                if (!keep && u == u_t) {
                    if (keep_all_ties) keep = true;
                    else {
                        uint32_t rank = 0;
                        for (uint32_t p = 0; p < cc2; p++)
                            rank += (s.cand[p] == u_t && s.cidx[p] < s.cidx[q]);
                        keep = (rank < A);
                    }
                }
                if (keep) outf[s.cidx[q]] = u2f(u);
            }
        } else {
            for (int i = tid; i < DCOLS; i += NT) {
                uint32_t u = f2u(rowf[i]);
                if ((u >> 21) != b1) continue;
                bool keep = (u > u_t);
                if (!keep && u == u_t) {
                    if (keep_all_ties) keep = true;
                    else {
                        uint32_t rank = 0;
                        for (int q = 0; q < i; q++) rank += (f2u(rowf[q]) == u_t);
                        keep = (rank < A);
                    }
                }
                if (keep) outf[i] = u2f(u);
            }
        }
        return;
    }

    // ================= FAST PATH: exact select over SMEM candidates =================
    const uint32_t kk = KKEEP - c_above;
    const int niterC = ((int)ccount + NT - 1) / NT;

    // pass A': bits [21,32)   (hist already cleared before the full-row pass)
    #pragma unroll 1
    for (int it = 0; it < niterC; it++) {
        int i = tid + it * NT;
        bool valid = i < (int)ccount;
        uint32_t u = valid ? s.cand[i] : 0;
        hist_add(s.hist, u >> 21, valid);
    }
    __syncthreads();
    if (tid < 32) select_from_top(s.hist, NBINS, kk, &s.bA, &s.kkA, &s.cntC);
    __syncthreads();
    const uint32_t b1 = s.bA;
    const uint32_t kk1 = s.kkA;

    // pass B': bits [10,21)
    {
        uint4* h4 = reinterpret_cast<uint4*>(s.hist);
        h4[tid] = make_uint4(0, 0, 0, 0);
    }
    __syncthreads();
    #pragma unroll 1
    for (int it = 0; it < niterC; it++) {
        int i = tid + it * NT;
        bool valid = i < (int)ccount;
        uint32_t u = valid ? s.cand[i] : 0;
        valid = valid && ((u >> 21) == b1);
        hist_add(s.hist, (u >> 10) & 0x7FFu, valid);
    }
    __syncthreads();
    if (tid < 32) select_from_top(s.hist, NBINS, kk1, &s.bB, &s.kkB, &s.cntC);
    __syncthreads();
    const uint32_t b2 = s.bB;
    const uint32_t kk2 = s.kkB;
    const uint32_t pref22 = (b1 << 11) | b2;

    // pass C': bits [0,10)
    for (int i = tid; i < 1024; i += NT) s.hist[i] = 0;
    __syncthreads();
    #pragma unroll 1
    for (int it = 0; it < niterC; it++) {
        int i = tid + it * NT;
        bool valid = i < (int)ccount;
        uint32_t u = valid ? s.cand[i] : 0;
        valid = valid && ((u >> 10) == pref22);
        hist_add(s.hist, u & 0x3FFu, valid);
    }
    __syncthreads();
    if (tid < 32) select_from_top(s.hist, 1024, kk2, &s.bC, &s.kkC, &s.cntC);
    __syncthreads();

    const uint32_t u_t = (b1 << 21) | (b2 << 10) | s.bC;  // exact k-th largest key
    const uint32_t A = s.kkC;
    const uint32_t T = s.cntC;
    const bool keep_all_ties = (A == T);

    // ---- fixup: scatter-write winners among candidates ----
    for (uint32_t q = tid; q < ccount; q += NT) {
        uint32_t u = s.cand[q];
        bool keep = (u > u_t);
        if (!keep && u == u_t) {
            if (keep_all_ties) keep = true;
            else {
                uint32_t rank = 0;
                for (uint32_t p = 0; p < ccount; p++)
                    rank += (s.cand[p] == u_t && s.cidx[p] < s.cidx[q]);
                keep = (rank < A);
            }
        }
        if (keep) outf[s.cidx[q]] = u2f(u);
    }
}

extern "C" void kernel_launch(void* const* d_in, const int* in_sizes, int n_in,
                              void* d_out, int out_size) {
    const float* in = (const float*)d_in[0];
    float* out = (float*)d_out;
    int rows = in_sizes[0] / DCOLS;   // 4096
    wta_kernel<<<rows, NT>>>(in, out, rows);
}